// round 11
// baseline (speedup 1.0000x reference)
#include <cuda_runtime.h>
#include <cuda_fp16.h>
#include <mma.h>
#include <stdint.h>

using namespace nvcuda;

#define N_NODES 50000
#define N_EDGES 800000
#define IN_C    128
#define HID_C   128
#define OUT_C   64
#define CAP     64          // ELL capacity per node (P(deg>48) ~ 1e-10)

typedef unsigned long long ull;
union H4 { uint2 u; __half2 h[2]; };
union H8 { uint4 u; __half2 h[4]; };

// ---------------- scratch (static device globals; zero-initialized) ----------
__device__ int    g_cnt  [N_NODES];           // ALWAYS zero between calls
__device__ int    g_len  [N_NODES];
__device__ int    g_ell  [N_NODES * CAP];     // ELL adjacency (by dst)
__device__ float  g_dinv [N_NODES];
__device__ __half g_xh   [N_NODES * IN_C];    // fp16 copy of x
__device__ __half g_w1hi [IN_C * HID_C];
__device__ __half g_w1lo [IN_C * HID_C];
__device__ __half g_w2hi [HID_C * OUT_C];
__device__ __half g_w2lo [HID_C * OUT_C];
__device__ __half g_h1   [N_NODES * HID_C];   // UNSCALED GEMM1 output (fp16)
__device__ __half g_x2h  [N_NODES * HID_C];   // relu(layer1) fp16
__device__ __half g_h2   [N_NODES * OUT_C];   // pre-scaled GEMM2 output (fp16)

// ---------------- input conversion: x -> fp16, W -> hi+lo fp16 ---------------
__global__ void k_convert(const float* __restrict__ x,
                          const float* __restrict__ W1,
                          const float* __restrict__ W2)
{
    int gt = blockIdx.x * blockDim.x + threadIdx.x;
    if (gt < N_NODES * IN_C / 4) {
        float4 v = reinterpret_cast<const float4*>(x)[gt];
        H4 h;
        h.h[0] = __floats2half2_rn(v.x, v.y);
        h.h[1] = __floats2half2_rn(v.z, v.w);
        reinterpret_cast<uint2*>(g_xh)[gt] = h.u;
    }
    if (gt < IN_C * HID_C) {
        float w = W1[gt];
        __half hi = __float2half_rn(w);
        g_w1hi[gt] = hi;
        g_w1lo[gt] = __float2half_rn(w - __half2float(hi));
    }
    if (gt < HID_C * OUT_C) {
        float w = W2[gt];
        __half hi = __float2half_rn(w);
        g_w2hi[gt] = hi;
        g_w2lo[gt] = __float2half_rn(w - __half2float(hi));
    }
}

// ---------------- ELL build: count + place in ONE kernel ----------------------
__global__ void k_place_ell(const int* __restrict__ src, const int* __restrict__ dst) {
    int t = blockIdx.x * blockDim.x + threadIdx.x;
    if (t >= N_EDGES / 4) return;
    int4 d4 = reinterpret_cast<const int4*>(dst)[t];
    int4 s4 = reinterpret_cast<const int4*>(src)[t];
    int i0 = atomicAdd(&g_cnt[d4.x], 1);
    int i1 = atomicAdd(&g_cnt[d4.y], 1);
    int i2 = atomicAdd(&g_cnt[d4.z], 1);
    int i3 = atomicAdd(&g_cnt[d4.w], 1);
    if (i0 < CAP) g_ell[d4.x * CAP + i0] = s4.x;
    if (i1 < CAP) g_ell[d4.y * CAP + i1] = s4.y;
    if (i2 < CAP) g_ell[d4.z * CAP + i2] = s4.z;
    if (i3 < CAP) g_ell[d4.w * CAP + i3] = s4.w;
}

__global__ void k_dinv() {
    int i = blockIdx.x * blockDim.x + threadIdx.x;
    if (i >= N_NODES) return;
    int c = g_cnt[i];
    g_len[i]  = (c < CAP) ? c : CAP;
    g_dinv[i] = rsqrtf(1.0f + (float)c);           // +1 self loop
    g_cnt[i]  = 0;                                 // restore zero invariant
}

// ---------------- GEMM via wmma: H = fp16( (Xh @ (Whi+Wlo)) [* dinv] ) -------
// 128-row x COUT tile per block, 8 warps; warp owns 16 rows x COUT cols.
template <int COUT, bool PRESCALE>
__global__ __launch_bounds__(256)
void k_gemm_wmma(const __half* __restrict__ Xh,
                 const __half* __restrict__ Whi,
                 const __half* __restrict__ Wlo,
                 __half* __restrict__ H)
{
    constexpr int LDX = 136;           // 272B rows (16B multiple, dodges conflicts)
    constexpr int NT  = COUT / 16;

    extern __shared__ char smem[];
    __half* xs  = reinterpret_cast<__half*>(smem);             // [128][LDX]
    __half* wsh = xs + 128 * LDX;                              // [128][COUT]
    __half* wsl = wsh + 128 * COUT;                            // [128][COUT]
    float*  stw = reinterpret_cast<float*>(wsl + 128 * COUT);  // [8][256]

    const int tid  = threadIdx.x;
    const int wid  = tid >> 5;
    const int lane = tid & 31;
    const int row0 = blockIdx.x * 128;

    // X tile: 128 rows x 128 halves (zero-fill OOB rows)
    for (int i = tid; i < 128 * 16; i += 256) {
        int r = i >> 4, q = i & 15;
        int gr = row0 + r;
        uint4 v = make_uint4(0, 0, 0, 0);
        if (gr < N_NODES)
            v = *reinterpret_cast<const uint4*>(Xh + (size_t)gr * IN_C + q * 8);
        *reinterpret_cast<uint4*>(xs + r * LDX + q * 8) = v;
    }
    // W hi/lo tiles
    for (int i = tid; i < 128 * COUT / 8; i += 256) {
        reinterpret_cast<uint4*>(wsh)[i] = reinterpret_cast<const uint4*>(Whi)[i];
        reinterpret_cast<uint4*>(wsl)[i] = reinterpret_cast<const uint4*>(Wlo)[i];
    }
    __syncthreads();

    wmma::fragment<wmma::accumulator, 16, 16, 16, float> acc[NT];
#pragma unroll
    for (int n = 0; n < NT; n++) wmma::fill_fragment(acc[n], 0.0f);

#pragma unroll
    for (int k0 = 0; k0 < 128; k0 += 16) {
        wmma::fragment<wmma::matrix_a, 16, 16, 16, __half, wmma::row_major> af;
        wmma::load_matrix_sync(af, xs + wid * 16 * LDX + k0, LDX);
#pragma unroll
        for (int n = 0; n < NT; n++) {
            wmma::fragment<wmma::matrix_b, 16, 16, 16, __half, wmma::row_major> bf;
            wmma::load_matrix_sync(bf, wsh + k0 * COUT + n * 16, COUT);
            wmma::mma_sync(acc[n], af, bf, acc[n]);
            wmma::load_matrix_sync(bf, wsl + k0 * COUT + n * 16, COUT);
            wmma::mma_sync(acc[n], af, bf, acc[n]);
        }
    }

    // copy-out: stage each 16x16 frag in smem, convert to fp16, 16B stores
    float* st = stw + wid * 256;
    const int r  = lane >> 1;
    const int c0 = (lane & 1) * 8;
    const int gr = row0 + wid * 16 + r;
    float dv = 1.0f;
    if (PRESCALE && gr < N_NODES) dv = g_dinv[gr];

#pragma unroll
    for (int n = 0; n < NT; n++) {
        wmma::store_matrix_sync(st, acc[n], 16, wmma::mem_row_major);
        __syncwarp();
        if (gr < N_NODES) {
            float4 f0 = *reinterpret_cast<float4*>(st + r * 16 + c0);
            float4 f1 = *reinterpret_cast<float4*>(st + r * 16 + c0 + 4);
            H8 o;
            o.h[0] = __floats2half2_rn(f0.x * dv, f0.y * dv);
            o.h[1] = __floats2half2_rn(f0.z * dv, f0.w * dv);
            o.h[2] = __floats2half2_rn(f1.x * dv, f1.y * dv);
            o.h[3] = __floats2half2_rn(f1.z * dv, f1.w * dv);
            *reinterpret_cast<uint4*>(H + (size_t)gr * COUT + n * 16 + c0) = o.u;
        }
        __syncwarp();
    }
}

// ---------------- layer-1 aggregation: warp per node, ELL, int4 indices -------
__global__ __launch_bounds__(256)
void k_agg1(const float* __restrict__ b1) {
    int gw   = (blockIdx.x * 256 + threadIdx.x) >> 5;
    int lane = threadIdx.x & 31;
    if (gw >= N_NODES) return;

    const uint2* Hq = reinterpret_cast<const uint2*>(g_h1);

#define UNPACK4(r, f01, f23) { H4 _t; _t.u = (r); \
        f01 = __half22float2(_t.h[0]); f23 = __half22float2(_t.h[1]); }

    float dvn = __ldg(&g_dinv[gw]);
    float4 a0, a1, a2, a3;
    {
        uint2 r = __ldcg(&Hq[(size_t)gw * 32 + lane]);
        float2 f01, f23; UNPACK4(r, f01, f23);
        a0 = make_float4(f01.x * dvn, f01.y * dvn, f23.x * dvn, f23.y * dvn);
    }
    a1 = make_float4(0.f, 0.f, 0.f, 0.f);
    a2 = make_float4(0.f, 0.f, 0.f, 0.f);
    a3 = make_float4(0.f, 0.f, 0.f, 0.f);

    const int len = __ldg(&g_len[gw]);
    const int4* E4 = reinterpret_cast<const int4*>(g_ell + gw * CAP);
    int f = 0;

    for (; f + 8 <= len; f += 8) {
        int4 ia = __ldg(&E4[(f >> 2) + 0]);
        int4 ib = __ldg(&E4[(f >> 2) + 1]);
        float d0 = __ldg(&g_dinv[ia.x]), d1 = __ldg(&g_dinv[ia.y]);
        float d2 = __ldg(&g_dinv[ia.z]), d3 = __ldg(&g_dinv[ia.w]);
        float d4 = __ldg(&g_dinv[ib.x]), d5 = __ldg(&g_dinv[ib.y]);
        float d6 = __ldg(&g_dinv[ib.z]), d7 = __ldg(&g_dinv[ib.w]);
        uint2 r0 = __ldcg(&Hq[(size_t)ia.x * 32 + lane]);
        uint2 r1 = __ldcg(&Hq[(size_t)ia.y * 32 + lane]);
        uint2 r2 = __ldcg(&Hq[(size_t)ia.z * 32 + lane]);
        uint2 r3 = __ldcg(&Hq[(size_t)ia.w * 32 + lane]);
        uint2 r4 = __ldcg(&Hq[(size_t)ib.x * 32 + lane]);
        uint2 r5 = __ldcg(&Hq[(size_t)ib.y * 32 + lane]);
        uint2 r6 = __ldcg(&Hq[(size_t)ib.z * 32 + lane]);
        uint2 r7 = __ldcg(&Hq[(size_t)ib.w * 32 + lane]);
        float2 f01, f23;
        UNPACK4(r0, f01, f23);
        a0.x = fmaf(f01.x, d0, a0.x); a0.y = fmaf(f01.y, d0, a0.y);
        a0.z = fmaf(f23.x, d0, a0.z); a0.w = fmaf(f23.y, d0, a0.w);
        UNPACK4(r1, f01, f23);
        a1.x = fmaf(f01.x, d1, a1.x); a1.y = fmaf(f01.y, d1, a1.y);
        a1.z = fmaf(f23.x, d1, a1.z); a1.w = fmaf(f23.y, d1, a1.w);
        UNPACK4(r2, f01, f23);
        a2.x = fmaf(f01.x, d2, a2.x); a2.y = fmaf(f01.y, d2, a2.y);
        a2.z = fmaf(f23.x, d2, a2.z); a2.w = fmaf(f23.y, d2, a2.w);
        UNPACK4(r3, f01, f23);
        a3.x = fmaf(f01.x, d3, a3.x); a3.y = fmaf(f01.y, d3, a3.y);
        a3.z = fmaf(f23.x, d3, a3.z); a3.w = fmaf(f23.y, d3, a3.w);
        UNPACK4(r4, f01, f23);
        a0.x = fmaf(f01.x, d4, a0.x); a0.y = fmaf(f01.y, d4, a0.y);
        a0.z = fmaf(f23.x, d4, a0.z); a0.w = fmaf(f23.y, d4, a0.w);
        UNPACK4(r5, f01, f23);
        a1.x = fmaf(f01.x, d5, a1.x); a1.y = fmaf(f01.y, d5, a1.y);
        a1.z = fmaf(f23.x, d5, a1.z); a1.w = fmaf(f23.y, d5, a1.w);
        UNPACK4(r6, f01, f23);
        a2.x = fmaf(f01.x, d6, a2.x); a2.y = fmaf(f01.y, d6, a2.y);
        a2.z = fmaf(f23.x, d6, a2.z); a2.w = fmaf(f23.y, d6, a2.w);
        UNPACK4(r7, f01, f23);
        a3.x = fmaf(f01.x, d7, a3.x); a3.y = fmaf(f01.y, d7, a3.y);
        a3.z = fmaf(f23.x, d7, a3.z); a3.w = fmaf(f23.y, d7, a3.w);
    }
    for (; f < len; f++) {
        int s = __ldg(&g_ell[gw * CAP + f]);
        float d = __ldg(&g_dinv[s]);
        uint2 r = __ldcg(&Hq[(size_t)s * 32 + lane]);
        float2 f01, f23; UNPACK4(r, f01, f23);
        a0.x = fmaf(f01.x, d, a0.x); a0.y = fmaf(f01.y, d, a0.y);
        a0.z = fmaf(f23.x, d, a0.z); a0.w = fmaf(f23.y, d, a0.w);
    }
    a0.x += a1.x + a2.x + a3.x;
    a0.y += a1.y + a2.y + a3.y;
    a0.z += a1.z + a2.z + a3.z;
    a0.w += a1.w + a2.w + a3.w;

    float4 b = reinterpret_cast<const float4*>(b1)[lane];
    float ox = fmaxf(fmaf(a0.x, dvn, b.x), 0.f);
    float oy = fmaxf(fmaf(a0.y, dvn, b.y), 0.f);
    float oz = fmaxf(fmaf(a0.z, dvn, b.z), 0.f);
    float ow = fmaxf(fmaf(a0.w, dvn, b.w), 0.f);
    H4 st;
    st.h[0] = __floats2half2_rn(ox, oy);
    st.h[1] = __floats2half2_rn(oz, ow);
    reinterpret_cast<uint2*>(g_x2h)[(size_t)gw * 32 + lane] = st.u;
}

// ---------------- layer-2 aggregation: half-warp per node, ELL ----------------
__global__ __launch_bounds__(256)
void k_agg2(float* __restrict__ out, const float* __restrict__ b2) {
    int gw   = (blockIdx.x * 256 + threadIdx.x) >> 5;
    int lane = threadIdx.x & 31;
    int n    = gw * 2 + (lane >> 4);
    int hl   = lane & 15;
    if (n >= N_NODES) return;

    const uint2* Hq = reinterpret_cast<const uint2*>(g_h2);

    float4 a0, a1, a2, a3;
    {
        uint2 r = __ldcg(&Hq[(size_t)n * 16 + hl]);
        float2 f01, f23; UNPACK4(r, f01, f23);
        a0 = make_float4(f01.x, f01.y, f23.x, f23.y);   // self (pre-scaled)
    }
    a1 = make_float4(0.f, 0.f, 0.f, 0.f);
    a2 = make_float4(0.f, 0.f, 0.f, 0.f);
    a3 = make_float4(0.f, 0.f, 0.f, 0.f);

    const int len = __ldg(&g_len[n]);
    const int4* E4 = reinterpret_cast<const int4*>(g_ell + n * CAP);
    int f = 0;

    for (; f + 8 <= len; f += 8) {
        int4 ia = __ldg(&E4[(f >> 2) + 0]);
        int4 ib = __ldg(&E4[(f >> 2) + 1]);
        uint2 r0 = __ldcg(&Hq[(size_t)ia.x * 16 + hl]);
        uint2 r1 = __ldcg(&Hq[(size_t)ia.y * 16 + hl]);
        uint2 r2 = __ldcg(&Hq[(size_t)ia.z * 16 + hl]);
        uint2 r3 = __ldcg(&Hq[(size_t)ia.w * 16 + hl]);
        uint2 r4 = __ldcg(&Hq[(size_t)ib.x * 16 + hl]);
        uint2 r5 = __ldcg(&Hq[(size_t)ib.y * 16 + hl]);
        uint2 r6 = __ldcg(&Hq[(size_t)ib.z * 16 + hl]);
        uint2 r7 = __ldcg(&Hq[(size_t)ib.w * 16 + hl]);
        float2 f01, f23;
        UNPACK4(r0, f01, f23);
        a0.x += f01.x; a0.y += f01.y; a0.z += f23.x; a0.w += f23.y;
        UNPACK4(r1, f01, f23);
        a1.x += f01.x; a1.y += f01.y; a1.z += f23.x; a1.w += f23.y;
        UNPACK4(r2, f01, f23);
        a2.x += f01.x; a2.y += f01.y; a2.z += f23.x; a2.w += f23.y;
        UNPACK4(r3, f01, f23);
        a3.x += f01.x; a3.y += f01.y; a3.z += f23.x; a3.w += f23.y;
        UNPACK4(r4, f01, f23);
        a0.x += f01.x; a0.y += f01.y; a0.z += f23.x; a0.w += f23.y;
        UNPACK4(r5, f01, f23);
        a1.x += f01.x; a1.y += f01.y; a1.z += f23.x; a1.w += f23.y;
        UNPACK4(r6, f01, f23);
        a2.x += f01.x; a2.y += f01.y; a2.z += f23.x; a2.w += f23.y;
        UNPACK4(r7, f01, f23);
        a3.x += f01.x; a3.y += f01.y; a3.z += f23.x; a3.w += f23.y;
    }
    for (; f < len; f++) {
        int s = __ldg(&g_ell[n * CAP + f]);
        uint2 r = __ldcg(&Hq[(size_t)s * 16 + hl]);
        float2 f01, f23; UNPACK4(r, f01, f23);
        a0.x += f01.x; a0.y += f01.y; a0.z += f23.x; a0.w += f23.y;
    }
    a0.x += a1.x + a2.x + a3.x;
    a0.y += a1.y + a2.y + a3.y;
    a0.z += a1.z + a2.z + a3.z;
    a0.w += a1.w + a2.w + a3.w;

    float dv = __ldg(&g_dinv[n]);
    float4 b = reinterpret_cast<const float4*>(b2)[hl];
    float4 o;
    o.x = fmaf(a0.x, dv, b.x);
    o.y = fmaf(a0.y, dv, b.y);
    o.z = fmaf(a0.z, dv, b.z);
    o.w = fmaf(a0.w, dv, b.w);
    reinterpret_cast<float4*>(out)[(size_t)n * 16 + hl] = o;
}

// ---------------- launch -------------------------------------------------------
extern "C" void kernel_launch(void* const* d_in, const int* in_sizes, int n_in,
                              void* d_out, int out_size)
{
    const float* x  = (const float*)d_in[0];
    const int*   ei = (const int*)  d_in[1];
    const float* W1 = (const float*)d_in[2];
    const float* b1 = (const float*)d_in[3];
    const float* W2 = (const float*)d_in[4];
    const float* b2 = (const float*)d_in[5];
    float* out = (float*)d_out;

    const int* srcp = ei;             // edge_index[0]
    const int* dstp = ei + N_EDGES;   // edge_index[1]

    __half *xh, *w1hi, *w1lo, *w2hi, *w2lo, *h1, *x2h, *h2;
    cudaGetSymbolAddress((void**)&xh,   g_xh);
    cudaGetSymbolAddress((void**)&w1hi, g_w1hi);
    cudaGetSymbolAddress((void**)&w1lo, g_w1lo);
    cudaGetSymbolAddress((void**)&w2hi, g_w2hi);
    cudaGetSymbolAddress((void**)&w2lo, g_w2lo);
    cudaGetSymbolAddress((void**)&h1,   g_h1);
    cudaGetSymbolAddress((void**)&x2h,  g_x2h);
    cudaGetSymbolAddress((void**)&h2,   g_h2);

    // smem sizes for the two wmma instantiations
    const int SM1 = 128 * 136 * 2 + 2 * 128 * HID_C * 2 + 8 * 256 * 4;  // 108544
    const int SM2 = 128 * 136 * 2 + 2 * 128 * OUT_C * 2 + 8 * 256 * 4;  //  75776

    static cudaStream_t s_aux = nullptr;
    static cudaEvent_t  e_fork = nullptr, e_join = nullptr;
    if (s_aux == nullptr) {
        cudaStreamCreateWithFlags(&s_aux, cudaStreamNonBlocking);
        cudaEventCreateWithFlags(&e_fork, cudaEventDisableTiming);
        cudaEventCreateWithFlags(&e_join, cudaEventDisableTiming);
        cudaFuncSetAttribute(k_gemm_wmma<HID_C, false>,
                             cudaFuncAttributeMaxDynamicSharedMemorySize, SM1);
        cudaFuncSetAttribute(k_gemm_wmma<OUT_C, true>,
                             cudaFuncAttributeMaxDynamicSharedMemorySize, SM2);
    }

    const int gemm_blocks = (N_NODES + 127) / 128;   // 391

    // fork point at the start of the call
    cudaEventRecord(e_fork, 0);
    cudaStreamWaitEvent(s_aux, e_fork, 0);

    // ---- aux: convert inputs to fp16, then GEMM1 (no dinv dependency) ----
    k_convert<<<(N_NODES * IN_C / 4 + 255) / 256, 256, 0, s_aux>>>(x, W1, W2);
    k_gemm_wmma<HID_C, false><<<gemm_blocks, 256, SM1, s_aux>>>(xh, w1hi, w1lo, h1);
    cudaEventRecord(e_join, s_aux);

    // ---- main: ELL build (overlaps aux) ----
    k_place_ell<<<(N_EDGES / 4 + 255) / 256, 256>>>(srcp, dstp);
    k_dinv     <<<(N_NODES + 255) / 256, 256>>>();

    // ---- join, then layer 1 aggregation ----
    cudaStreamWaitEvent(0, e_join, 0);
    k_agg1<<<(N_NODES * 32 + 255) / 256, 256>>>(b1);

    // ---- layer 2 ----
    k_gemm_wmma<OUT_C, true><<<gemm_blocks, 256, SM2, 0>>>(x2h, w2hi, w2lo, h2);
    k_agg2<<<((N_NODES + 1) / 2 * 32 + 255) / 256, 256>>>(out, b2);
}

// round 12
// speedup vs baseline: 1.2770x; 1.2770x over previous
#include <cuda_runtime.h>
#include <cuda_fp16.h>
#include <stdint.h>

#define N_NODES 50000
#define N_EDGES 800000
#define IN_C    128
#define HID_C   128
#define OUT_C   64
#define CAP     64          // ELL capacity per node (P(deg>48) ~ 1e-10)

typedef unsigned long long ull;
union F2U { ull u; float2 f; };
union H4  { uint2 u; __half2 h[2]; };

// ---------------- scratch (static device globals; zero-initialized) ----------
__device__ int     g_cnt  [N_NODES];           // ALWAYS zero between calls
__device__ int     g_len  [N_NODES];
__device__ int     g_ell  [N_NODES * CAP];     // ELL adjacency (by dst)
__device__ float   g_dinv [N_NODES];
__device__ __half2 g_dinvh[N_NODES];           // (dinv, dinv) fp16 pair
__device__ __half  g_h1   [N_NODES * HID_C];   // UNSCALED GEMM1 output (fp16)
__device__ float   g_x2   [N_NODES * HID_C];
__device__ __half  g_h2   [N_NODES * OUT_C];   // pre-scaled GEMM2 output (fp16)

// ---------------- packed fp32x2 FMA ------------------------------------------
__device__ __forceinline__ ull fma2(ull a, ull b, ull c) {
    ull d;
    asm("fma.rn.f32x2 %0, %1, %2, %3;" : "=l"(d) : "l"(a), "l"(b), "l"(c));
    return d;
}

// ---------------- ELL build: count + place in ONE kernel ----------------------
__global__ void k_place_ell(const int* __restrict__ src, const int* __restrict__ dst) {
    int t = blockIdx.x * blockDim.x + threadIdx.x;
    if (t >= N_EDGES / 4) return;
    int4 d4 = reinterpret_cast<const int4*>(dst)[t];
    int4 s4 = reinterpret_cast<const int4*>(src)[t];
    int i0 = atomicAdd(&g_cnt[d4.x], 1);
    int i1 = atomicAdd(&g_cnt[d4.y], 1);
    int i2 = atomicAdd(&g_cnt[d4.z], 1);
    int i3 = atomicAdd(&g_cnt[d4.w], 1);
    if (i0 < CAP) g_ell[d4.x * CAP + i0] = s4.x;
    if (i1 < CAP) g_ell[d4.y * CAP + i1] = s4.y;
    if (i2 < CAP) g_ell[d4.z * CAP + i2] = s4.z;
    if (i3 < CAP) g_ell[d4.w * CAP + i3] = s4.w;
}

__global__ void k_dinv() {
    int i = blockIdx.x * blockDim.x + threadIdx.x;
    if (i >= N_NODES) return;
    int c = g_cnt[i];
    float dv = rsqrtf(1.0f + (float)c);            // +1 self loop
    g_len[i]   = (c < CAP) ? c : CAP;
    g_dinv[i]  = dv;
    g_dinvh[i] = __float2half2_rn(dv);
    g_cnt[i]   = 0;                                // restore zero invariant
}

// ---------------- GEMM: H = fp16( (X @ W) [* dinv[row]] ), packed fp32x2 -----
template <int COUT, bool PRESCALE>
__global__ __launch_bounds__(256)
void k_gemm(const float* __restrict__ X, const float* __restrict__ W,
            __half* __restrict__ H)
{
    constexpr int BM  = 64;
    constexpr int BK  = 32;
    constexpr int CQ  = COUT / 4;      // 32 / 16
    constexpr int RT  = 256 / CQ;      // 8 / 16
    constexpr int RPT = BM / RT;       // 8 / 4
    constexpr int XW  = 2 * BM + 4;    // 132 floats: 16B-aligned rows

    __shared__ float sXT2[BK][XW];     // duplicated transposed X tile
    __shared__ float sW  [BK][COUT];   // plain W tile

    const int tid  = threadIdx.x;
    const int colq = tid % CQ;
    const int rgrp = tid / CQ;
    const int row0 = blockIdx.x * BM;

    ull acc[RPT][2];
#pragma unroll
    for (int i = 0; i < RPT; i++) { acc[i][0] = 0ull; acc[i][1] = 0ull; }

    for (int k0 = 0; k0 < IN_C; k0 += BK) {
#pragma unroll
        for (int i = tid; i < BM * BK / 4; i += 256) {
            int r = i >> 3, q = i & 7;
            int gr = row0 + r;
            float4 v = make_float4(0.f, 0.f, 0.f, 0.f);
            if (gr < N_NODES)
                v = *reinterpret_cast<const float4*>(X + (size_t)gr * IN_C + k0 + 4 * q);
            *reinterpret_cast<float2*>(&sXT2[4 * q + 0][2 * r]) = make_float2(v.x, v.x);
            *reinterpret_cast<float2*>(&sXT2[4 * q + 1][2 * r]) = make_float2(v.y, v.y);
            *reinterpret_cast<float2*>(&sXT2[4 * q + 2][2 * r]) = make_float2(v.z, v.z);
            *reinterpret_cast<float2*>(&sXT2[4 * q + 3][2 * r]) = make_float2(v.w, v.w);
        }
        {
            const float4* wsrc = reinterpret_cast<const float4*>(W + (size_t)k0 * COUT);
            float4* wdst = reinterpret_cast<float4*>(&sW[0][0]);
#pragma unroll
            for (int i = tid; i < BK * COUT / 4; i += 256) wdst[i] = wsrc[i];
        }
        __syncthreads();

#pragma unroll
        for (int k = 0; k < BK; k++) {
            ulonglong2 w = *reinterpret_cast<const ulonglong2*>(&sW[k][4 * colq]);
            ull ad[RPT];
            const ulonglong2* aq =
                reinterpret_cast<const ulonglong2*>(&sXT2[k][2 * rgrp * RPT]);
#pragma unroll
            for (int p = 0; p < RPT / 2; p++) {
                ulonglong2 t = aq[p];
                ad[2 * p + 0] = t.x;
                ad[2 * p + 1] = t.y;
            }
#pragma unroll
            for (int i = 0; i < RPT; i++) {
                acc[i][0] = fma2(ad[i], w.x, acc[i][0]);
                acc[i][1] = fma2(ad[i], w.y, acc[i][1]);
            }
        }
        __syncthreads();
    }

#pragma unroll
    for (int i = 0; i < RPT; i++) {
        int gr = row0 + rgrp * RPT + i;
        if (gr < N_NODES) {
            F2U p0, p1;
            p0.u = acc[i][0]; p1.u = acc[i][1];
            float4 o = make_float4(p0.f.x, p0.f.y, p1.f.x, p1.f.y);
            if (PRESCALE) {
                float dv = g_dinv[gr];
                o.x *= dv; o.y *= dv; o.z *= dv; o.w *= dv;
            }
            H4 st;
            st.h[0] = __floats2half2_rn(o.x, o.y);
            st.h[1] = __floats2half2_rn(o.z, o.w);
            *reinterpret_cast<uint2*>(H + (size_t)gr * COUT + 4 * colq) = st.u;
        }
    }
}

// ---------------- layer-1 aggregation: warp per node, HFMA2 accumulation ------
// x2[n] = relu( dinv[n] * (h1[n]*dinv[n] ... ) + b1 ); edge terms in fp16.
__global__ __launch_bounds__(256)
void k_agg1(const float* __restrict__ b1) {
    int gw   = (blockIdx.x * 256 + threadIdx.x) >> 5;
    int lane = threadIdx.x & 31;
    if (gw >= N_NODES) return;

    const uint2* Hq = reinterpret_cast<const uint2*>(g_h1);

    float dvn = __ldg(&g_dinv[gw]);
    // self loop in fp32
    float4 sf;
    {
        H4 t; t.u = __ldcg(&Hq[(size_t)gw * 32 + lane]);
        float2 f01 = __half22float2(t.h[0]);
        float2 f23 = __half22float2(t.h[1]);
        sf = make_float4(f01.x * dvn, f01.y * dvn, f23.x * dvn, f23.y * dvn);
    }

    const __half2 z = __float2half2_rn(0.f);
    __half2 a0l = z, a0h = z, a1l = z, a1h = z;
    __half2 a2l = z, a2h = z, a3l = z, a3h = z;

    const int len = __ldg(&g_len[gw]);
    const int4* E4 = reinterpret_cast<const int4*>(g_ell + gw * CAP);
    int f = 0;

    for (; f + 8 <= len; f += 8) {
        int4 ia = __ldg(&E4[(f >> 2) + 0]);
        int4 ib = __ldg(&E4[(f >> 2) + 1]);
        __half2 d0 = __ldg(&g_dinvh[ia.x]), d1 = __ldg(&g_dinvh[ia.y]);
        __half2 d2 = __ldg(&g_dinvh[ia.z]), d3 = __ldg(&g_dinvh[ia.w]);
        __half2 d4 = __ldg(&g_dinvh[ib.x]), d5 = __ldg(&g_dinvh[ib.y]);
        __half2 d6 = __ldg(&g_dinvh[ib.z]), d7 = __ldg(&g_dinvh[ib.w]);
        H4 t0, t1, t2, t3, t4, t5, t6, t7;
        t0.u = __ldcg(&Hq[(size_t)ia.x * 32 + lane]);
        t1.u = __ldcg(&Hq[(size_t)ia.y * 32 + lane]);
        t2.u = __ldcg(&Hq[(size_t)ia.z * 32 + lane]);
        t3.u = __ldcg(&Hq[(size_t)ia.w * 32 + lane]);
        t4.u = __ldcg(&Hq[(size_t)ib.x * 32 + lane]);
        t5.u = __ldcg(&Hq[(size_t)ib.y * 32 + lane]);
        t6.u = __ldcg(&Hq[(size_t)ib.z * 32 + lane]);
        t7.u = __ldcg(&Hq[(size_t)ib.w * 32 + lane]);
        a0l = __hfma2(t0.h[0], d0, a0l); a0h = __hfma2(t0.h[1], d0, a0h);
        a1l = __hfma2(t1.h[0], d1, a1l); a1h = __hfma2(t1.h[1], d1, a1h);
        a2l = __hfma2(t2.h[0], d2, a2l); a2h = __hfma2(t2.h[1], d2, a2h);
        a3l = __hfma2(t3.h[0], d3, a3l); a3h = __hfma2(t3.h[1], d3, a3h);
        a0l = __hfma2(t4.h[0], d4, a0l); a0h = __hfma2(t4.h[1], d4, a0h);
        a1l = __hfma2(t5.h[0], d5, a1l); a1h = __hfma2(t5.h[1], d5, a1h);
        a2l = __hfma2(t6.h[0], d6, a2l); a2h = __hfma2(t6.h[1], d6, a2h);
        a3l = __hfma2(t7.h[0], d7, a3l); a3h = __hfma2(t7.h[1], d7, a3h);
    }
    // remainder: rotate across the 4 accumulator sets
    for (int k = 0; f < len; f++, k++) {
        int s = __ldg(&g_ell[gw * CAP + f]);
        __half2 d = __ldg(&g_dinvh[s]);
        H4 t; t.u = __ldcg(&Hq[(size_t)s * 32 + lane]);
        switch (k & 3) {
        case 0: a0l = __hfma2(t.h[0], d, a0l); a0h = __hfma2(t.h[1], d, a0h); break;
        case 1: a1l = __hfma2(t.h[0], d, a1l); a1h = __hfma2(t.h[1], d, a1h); break;
        case 2: a2l = __hfma2(t.h[0], d, a2l); a2h = __hfma2(t.h[1], d, a2h); break;
        default: a3l = __hfma2(t.h[0], d, a3l); a3h = __hfma2(t.h[1], d, a3h); break;
        }
    }

    // merge in fp32
    float2 m0 = __half22float2(a0l), m1 = __half22float2(a1l);
    float2 m2 = __half22float2(a2l), m3 = __half22float2(a3l);
    float2 n0 = __half22float2(a0h), n1 = __half22float2(a1h);
    float2 n2 = __half22float2(a2h), n3 = __half22float2(a3h);
    float rx = sf.x + (m0.x + m1.x) + (m2.x + m3.x);
    float ry = sf.y + (m0.y + m1.y) + (m2.y + m3.y);
    float rz = sf.z + (n0.x + n1.x) + (n2.x + n3.x);
    float rw = sf.w + (n0.y + n1.y) + (n2.y + n3.y);

    float4 b = reinterpret_cast<const float4*>(b1)[lane];
    float4 o;
    o.x = fmaxf(fmaf(rx, dvn, b.x), 0.f);
    o.y = fmaxf(fmaf(ry, dvn, b.y), 0.f);
    o.z = fmaxf(fmaf(rz, dvn, b.z), 0.f);
    o.w = fmaxf(fmaf(rw, dvn, b.w), 0.f);
    reinterpret_cast<float4*>(g_x2)[(size_t)gw * 32 + lane] = o;
}

// ---------------- layer-2 aggregation: half-warp per node, HADD2 --------------
__global__ __launch_bounds__(256)
void k_agg2(float* __restrict__ out, const float* __restrict__ b2) {
    int gw   = (blockIdx.x * 256 + threadIdx.x) >> 5;
    int lane = threadIdx.x & 31;
    int n    = gw * 2 + (lane >> 4);
    int hl   = lane & 15;
    if (n >= N_NODES) return;

    const uint2* Hq = reinterpret_cast<const uint2*>(g_h2);

    // self loop in fp32 (pre-scaled)
    float4 sf;
    {
        H4 t; t.u = __ldcg(&Hq[(size_t)n * 16 + hl]);
        float2 f01 = __half22float2(t.h[0]);
        float2 f23 = __half22float2(t.h[1]);
        sf = make_float4(f01.x, f01.y, f23.x, f23.y);
    }

    const __half2 z = __float2half2_rn(0.f);
    __half2 a0l = z, a0h = z, a1l = z, a1h = z;
    __half2 a2l = z, a2h = z, a3l = z, a3h = z;

    const int len = __ldg(&g_len[n]);
    const int4* E4 = reinterpret_cast<const int4*>(g_ell + n * CAP);
    int f = 0;

    for (; f + 8 <= len; f += 8) {
        int4 ia = __ldg(&E4[(f >> 2) + 0]);
        int4 ib = __ldg(&E4[(f >> 2) + 1]);
        H4 t0, t1, t2, t3, t4, t5, t6, t7;
        t0.u = __ldcg(&Hq[(size_t)ia.x * 16 + hl]);
        t1.u = __ldcg(&Hq[(size_t)ia.y * 16 + hl]);
        t2.u = __ldcg(&Hq[(size_t)ia.z * 16 + hl]);
        t3.u = __ldcg(&Hq[(size_t)ia.w * 16 + hl]);
        t4.u = __ldcg(&Hq[(size_t)ib.x * 16 + hl]);
        t5.u = __ldcg(&Hq[(size_t)ib.y * 16 + hl]);
        t6.u = __ldcg(&Hq[(size_t)ib.z * 16 + hl]);
        t7.u = __ldcg(&Hq[(size_t)ib.w * 16 + hl]);
        a0l = __hadd2(t0.h[0], a0l); a0h = __hadd2(t0.h[1], a0h);
        a1l = __hadd2(t1.h[0], a1l); a1h = __hadd2(t1.h[1], a1h);
        a2l = __hadd2(t2.h[0], a2l); a2h = __hadd2(t2.h[1], a2h);
        a3l = __hadd2(t3.h[0], a3l); a3h = __hadd2(t3.h[1], a3h);
        a0l = __hadd2(t4.h[0], a0l); a0h = __hadd2(t4.h[1], a0h);
        a1l = __hadd2(t5.h[0], a1l); a1h = __hadd2(t5.h[1], a1h);
        a2l = __hadd2(t6.h[0], a2l); a2h = __hadd2(t6.h[1], a2h);
        a3l = __hadd2(t7.h[0], a3l); a3h = __hadd2(t7.h[1], a3h);
    }
    for (int k = 0; f < len; f++, k++) {
        int s = __ldg(&g_ell[n * CAP + f]);
        H4 t; t.u = __ldcg(&Hq[(size_t)s * 16 + hl]);
        switch (k & 3) {
        case 0: a0l = __hadd2(t.h[0], a0l); a0h = __hadd2(t.h[1], a0h); break;
        case 1: a1l = __hadd2(t.h[0], a1l); a1h = __hadd2(t.h[1], a1h); break;
        case 2: a2l = __hadd2(t.h[0], a2l); a2h = __hadd2(t.h[1], a2h); break;
        default: a3l = __hadd2(t.h[0], a3l); a3h = __hadd2(t.h[1], a3h); break;
        }
    }

    float2 m0 = __half22float2(a0l), m1 = __half22float2(a1l);
    float2 m2 = __half22float2(a2l), m3 = __half22float2(a3l);
    float2 n0 = __half22float2(a0h), n1 = __half22float2(a1h);
    float2 n2 = __half22float2(a2h), n3 = __half22float2(a3h);
    float rx = sf.x + (m0.x + m1.x) + (m2.x + m3.x);
    float ry = sf.y + (m0.y + m1.y) + (m2.y + m3.y);
    float rz = sf.z + (n0.x + n1.x) + (n2.x + n3.x);
    float rw = sf.w + (n0.y + n1.y) + (n2.y + n3.y);

    float dv = __ldg(&g_dinv[n]);
    float4 b = reinterpret_cast<const float4*>(b2)[hl];
    float4 o;
    o.x = fmaf(rx, dv, b.x);
    o.y = fmaf(ry, dv, b.y);
    o.z = fmaf(rz, dv, b.z);
    o.w = fmaf(rw, dv, b.w);
    reinterpret_cast<float4*>(out)[(size_t)n * 16 + hl] = o;
}

// ---------------- launch -------------------------------------------------------
extern "C" void kernel_launch(void* const* d_in, const int* in_sizes, int n_in,
                              void* d_out, int out_size)
{
    const float* x  = (const float*)d_in[0];
    const int*   ei = (const int*)  d_in[1];
    const float* W1 = (const float*)d_in[2];
    const float* b1 = (const float*)d_in[3];
    const float* W2 = (const float*)d_in[4];
    const float* b2 = (const float*)d_in[5];
    float* out = (float*)d_out;

    const int* srcp = ei;             // edge_index[0]
    const int* dstp = ei + N_EDGES;   // edge_index[1]

    __half *h1, *h2;
    float *x2;
    cudaGetSymbolAddress((void**)&h1, g_h1);
    cudaGetSymbolAddress((void**)&x2, g_x2);
    cudaGetSymbolAddress((void**)&h2, g_h2);

    static cudaStream_t s_aux = nullptr;
    static cudaEvent_t  e_fork = nullptr, e_join = nullptr;
    if (s_aux == nullptr) {
        cudaStreamCreateWithFlags(&s_aux, cudaStreamNonBlocking);
        cudaEventCreateWithFlags(&e_fork, cudaEventDisableTiming);
        cudaEventCreateWithFlags(&e_join, cudaEventDisableTiming);
    }

    const int gemm_blocks = (N_NODES + 63) / 64;

    // fork point at the start of the call (main stream)
    cudaEventRecord(e_fork, 0);
    cudaStreamWaitEvent(s_aux, e_fork, 0);

    // ---- GEMM1 on aux (no dinv dependency) ----
    k_gemm<HID_C, false><<<gemm_blocks, 256, 0, s_aux>>>(x, W1, h1);
    cudaEventRecord(e_join, s_aux);

    // ---- ELL build on the main stream (hidden under GEMM1): 2 kernels ----
    k_place_ell<<<(N_EDGES / 4 + 255) / 256, 256>>>(srcp, dstp);
    k_dinv     <<<(N_NODES + 255) / 256, 256>>>();

    // ---- join, then layer 1 aggregation ----
    cudaStreamWaitEvent(0, e_join, 0);
    k_agg1<<<(N_NODES * 32 + 255) / 256, 256>>>(b1);

    // ---- layer 2 ----
    k_gemm<OUT_C, true><<<gemm_blocks, 256>>>(x2, W2, h2);
    k_agg2<<<((N_NODES + 1) / 2 * 32 + 255) / 256, 256>>>(out, b2);
}

// round 13
// speedup vs baseline: 1.8591x; 1.4558x over previous
#include <cuda_runtime.h>
#include <cuda_fp16.h>
#include <stdint.h>

#define N_NODES 50000
#define N_EDGES 800000
#define IN_C    128
#define HID_C   128
#define OUT_C   64
#define CAP     64          // ELL capacity per node (P(deg>48) ~ 1e-10)

typedef unsigned long long ull;
union H4 { uint2 u; __half2 h[2]; };
union H8 { uint4 u; __half2 h[4]; };

// ---------------- scratch (static device globals; zero-initialized) ----------
__device__ int    g_cnt [N_NODES];           // ALWAYS zero between calls
__device__ int    g_len [N_NODES];
__device__ int    g_ell [N_NODES * CAP];     // ELL adjacency (by dst)
__device__ float  g_dinv[N_NODES];
__device__ __half g_h1  [N_NODES * HID_C];   // UNSCALED GEMM1 output (fp16)
__device__ float  g_x2  [N_NODES * HID_C];
__device__ __half g_h2  [N_NODES * OUT_C];   // pre-scaled GEMM2 output (fp16)

// ---------------- PTX helpers --------------------------------------------------
__device__ __forceinline__ uint32_t smem_u32(const void* p) {
    uint32_t a;
    asm("{ .reg .u64 t; cvta.to.shared.u64 t, %1; cvt.u32.u64 %0, t; }"
        : "=r"(a) : "l"(p));
    return a;
}

__device__ __forceinline__ void ldsm_x4(uint32_t& r0, uint32_t& r1,
                                        uint32_t& r2, uint32_t& r3, uint32_t addr) {
    asm volatile("ldmatrix.sync.aligned.m8n8.x4.shared.b16 {%0,%1,%2,%3}, [%4];"
                 : "=r"(r0), "=r"(r1), "=r"(r2), "=r"(r3) : "r"(addr));
}

__device__ __forceinline__ void ldsm_x4_t(uint32_t& r0, uint32_t& r1,
                                          uint32_t& r2, uint32_t& r3, uint32_t addr) {
    asm volatile("ldmatrix.sync.aligned.m8n8.x4.trans.shared.b16 {%0,%1,%2,%3}, [%4];"
                 : "=r"(r0), "=r"(r1), "=r"(r2), "=r"(r3) : "r"(addr));
}

__device__ __forceinline__ void mma16816(float* c, const uint32_t* a,
                                         uint32_t b0, uint32_t b1) {
    asm volatile("mma.sync.aligned.m16n8k16.row.col.f32.f16.f16.f32 "
                 "{%0,%1,%2,%3}, {%4,%5,%6,%7}, {%8,%9}, {%0,%1,%2,%3};"
                 : "+f"(c[0]), "+f"(c[1]), "+f"(c[2]), "+f"(c[3])
                 : "r"(a[0]), "r"(a[1]), "r"(a[2]), "r"(a[3]), "r"(b0), "r"(b1));
}

// ---------------- ELL build: count + place in ONE kernel ----------------------
__global__ void k_place_ell(const int* __restrict__ src, const int* __restrict__ dst) {
    int t = blockIdx.x * blockDim.x + threadIdx.x;
    if (t >= N_EDGES / 4) return;
    int4 d4 = reinterpret_cast<const int4*>(dst)[t];
    int4 s4 = reinterpret_cast<const int4*>(src)[t];
    int i0 = atomicAdd(&g_cnt[d4.x], 1);
    int i1 = atomicAdd(&g_cnt[d4.y], 1);
    int i2 = atomicAdd(&g_cnt[d4.z], 1);
    int i3 = atomicAdd(&g_cnt[d4.w], 1);
    if (i0 < CAP) g_ell[d4.x * CAP + i0] = s4.x;
    if (i1 < CAP) g_ell[d4.y * CAP + i1] = s4.y;
    if (i2 < CAP) g_ell[d4.z * CAP + i2] = s4.z;
    if (i3 < CAP) g_ell[d4.w * CAP + i3] = s4.w;
}

__global__ void k_dinv() {
    int i = blockIdx.x * blockDim.x + threadIdx.x;
    if (i >= N_NODES) return;
    int c = g_cnt[i];
    g_len[i]  = (c < CAP) ? c : CAP;
    g_dinv[i] = rsqrtf(1.0f + (float)c);           // +1 self loop
    g_cnt[i]  = 0;                                 // restore zero invariant
}

// ---------------- GEMM via mma.sync m16n8k16 ----------------------------------
// 128 rows x COUT per block, 128 threads (4 warps); warp owns 32 rows.
// A and W converted fp32->fp16 into SW128-swizzled 128B-row subtiles.
// K = 128 fixed (IN_C == HID_C).
template <int COUT, bool PRESCALE>
__global__ __launch_bounds__(128)
void k_gemm_mma(const float* __restrict__ X, const float* __restrict__ W,
                __half* __restrict__ H)
{
    constexpr int NT   = COUT / 8;      // n8 tiles: 16 / 8
    constexpr int NJP  = NT / 2;        // tile pairs: 8 / 4
    constexpr int SUBB = 16384;         // bytes per 128x64-half subtile

    extern __shared__ char smem[];
    char* sA = smem;                    // 2 subtiles = 32 KB
    char* sW = smem + 2 * SUBB;         // COUT/64 subtiles

    const int tid  = threadIdx.x;
    const int wid  = tid >> 5;
    const int lane = tid & 31;
    const int row0 = blockIdx.x * 128;

    // ---- load X tile: fp32 -> fp16, swizzled 16B stores ----
    for (int i = tid; i < 128 * 16; i += 128) {
        int r = i >> 4, g = i & 15;
        int gr = row0 + r;
        float4 v0 = make_float4(0.f, 0.f, 0.f, 0.f);
        float4 v1 = v0;
        if (gr < N_NODES) {
            const float4* p = reinterpret_cast<const float4*>(X + (size_t)gr * IN_C + g * 8);
            v0 = p[0]; v1 = p[1];
        }
        H8 h;
        h.h[0] = __floats2half2_rn(v0.x, v0.y);
        h.h[1] = __floats2half2_rn(v0.z, v0.w);
        h.h[2] = __floats2half2_rn(v1.x, v1.y);
        h.h[3] = __floats2half2_rn(v1.z, v1.w);
        int sub = g >> 3, gg = g & 7;
        int off = r * 128 + gg * 16;
        off ^= (off >> 3) & 0x70;
        *reinterpret_cast<uint4*>(sA + sub * SUBB + off) = h.u;
    }
    // ---- load W tile: fp32 -> fp16, swizzled ----
    for (int i = tid; i < 128 * (COUT / 8); i += 128) {
        int r = i / (COUT / 8), g = i % (COUT / 8);
        const float4* p = reinterpret_cast<const float4*>(W + (size_t)r * COUT + g * 8);
        float4 v0 = p[0], v1 = p[1];
        H8 h;
        h.h[0] = __floats2half2_rn(v0.x, v0.y);
        h.h[1] = __floats2half2_rn(v0.z, v0.w);
        h.h[2] = __floats2half2_rn(v1.x, v1.y);
        h.h[3] = __floats2half2_rn(v1.z, v1.w);
        int sub = g >> 3, gg = g & 7;
        int off = r * 128 + gg * 16;
        off ^= (off >> 3) & 0x70;
        *reinterpret_cast<uint4*>(sW + sub * SUBB + off) = h.u;
    }
    __syncthreads();

    const uint32_t sA32 = smem_u32(sA);
    const uint32_t sW32 = smem_u32(sW);

    // lane constants for ldmatrix addressing (rows ≡ 0 mod 8 per tile)
    const int arow = (lane & 7) + ((lane & 8) ? 8 : 0);  // row within 16
    const int cgb  = (lane >> 4) & 1;                    // 16B-group select
    const int xorv = (lane & 7) << 4;                    // swizzle xor (bits 4-6)

    float acc[2][NT][4];
#pragma unroll
    for (int mt = 0; mt < 2; mt++)
#pragma unroll
        for (int nt = 0; nt < NT; nt++)
#pragma unroll
            for (int q = 0; q < 4; q++) acc[mt][nt][q] = 0.f;

    const int R = wid * 32;   // warp rows R..R+31 (2 m16 tiles)

#pragma unroll
    for (int ks = 0; ks < 8; ks++) {
        uint32_t a[2][4];
        const int subA = ks >> 2;
        const int grpA = (ks & 3) * 2 + cgb;
#pragma unroll
        for (int mt = 0; mt < 2; mt++) {
            int off = (R + mt * 16 + arow) * 128 + ((grpA * 16) ^ xorv);
            ldsm_x4(a[mt][0], a[mt][1], a[mt][2], a[mt][3],
                    sA32 + subA * SUBB + off);
        }
#pragma unroll
        for (int jp = 0; jp < NJP; jp++) {
            uint32_t b0, b1, b2, b3;
            const int subB = jp >> 2;
            const int grpB = (jp & 3) * 2 + cgb;
            int off = (ks * 16 + arow) * 128 + ((grpB * 16) ^ xorv);
            ldsm_x4_t(b0, b1, b2, b3, sW32 + subB * SUBB + off);
#pragma unroll
            for (int mt = 0; mt < 2; mt++) {
                mma16816(acc[mt][2 * jp + 0], a[mt], b0, b1);
                mma16816(acc[mt][2 * jp + 1], a[mt], b2, b3);
            }
        }
    }

    // ---- epilogue: fp32 acc -> (optional dinv scale) -> fp16 half2 stores ----
    const int erow = lane >> 2;          // 0..7
    const int ecol = (lane & 3) * 2;
#pragma unroll
    for (int mt = 0; mt < 2; mt++) {
        int gr0 = row0 + R + mt * 16 + erow;
        int gr1 = gr0 + 8;
        float dv0 = 1.f, dv1 = 1.f;
        if (PRESCALE) {
            if (gr0 < N_NODES) dv0 = g_dinv[gr0];
            if (gr1 < N_NODES) dv1 = g_dinv[gr1];
        }
#pragma unroll
        for (int nt = 0; nt < NT; nt++) {
            if (gr0 < N_NODES) {
                __half2 h = __floats2half2_rn(acc[mt][nt][0] * dv0,
                                              acc[mt][nt][1] * dv0);
                *reinterpret_cast<__half2*>(H + (size_t)gr0 * COUT + nt * 8 + ecol) = h;
            }
            if (gr1 < N_NODES) {
                __half2 h = __floats2half2_rn(acc[mt][nt][2] * dv1,
                                              acc[mt][nt][3] * dv1);
                *reinterpret_cast<__half2*>(H + (size_t)gr1 * COUT + nt * 8 + ecol) = h;
            }
        }
    }
}

// ---------------- layer-1 aggregation: warp per node, ELL, fp32 FMA (R10) -----
__global__ __launch_bounds__(256)
void k_agg1(const float* __restrict__ b1) {
    int gw   = (blockIdx.x * 256 + threadIdx.x) >> 5;
    int lane = threadIdx.x & 31;
    if (gw >= N_NODES) return;

    const uint2* Hq = reinterpret_cast<const uint2*>(g_h1);

#define UNPACK4(r, f01, f23) { H4 _t; _t.u = (r); \
        f01 = __half22float2(_t.h[0]); f23 = __half22float2(_t.h[1]); }

    float dvn = __ldg(&g_dinv[gw]);
    float4 a0, a1, a2, a3;
    {
        uint2 r = __ldcg(&Hq[(size_t)gw * 32 + lane]);
        float2 f01, f23; UNPACK4(r, f01, f23);
        a0 = make_float4(f01.x * dvn, f01.y * dvn, f23.x * dvn, f23.y * dvn);
    }
    a1 = make_float4(0.f, 0.f, 0.f, 0.f);
    a2 = make_float4(0.f, 0.f, 0.f, 0.f);
    a3 = make_float4(0.f, 0.f, 0.f, 0.f);

    const int len = __ldg(&g_len[gw]);
    const int4* E4 = reinterpret_cast<const int4*>(g_ell + gw * CAP);
    int f = 0;

    for (; f + 8 <= len; f += 8) {
        int4 ia = __ldg(&E4[(f >> 2) + 0]);
        int4 ib = __ldg(&E4[(f >> 2) + 1]);
        float d0 = __ldg(&g_dinv[ia.x]), d1 = __ldg(&g_dinv[ia.y]);
        float d2 = __ldg(&g_dinv[ia.z]), d3 = __ldg(&g_dinv[ia.w]);
        float d4 = __ldg(&g_dinv[ib.x]), d5 = __ldg(&g_dinv[ib.y]);
        float d6 = __ldg(&g_dinv[ib.z]), d7 = __ldg(&g_dinv[ib.w]);
        uint2 r0 = __ldcg(&Hq[(size_t)ia.x * 32 + lane]);
        uint2 r1 = __ldcg(&Hq[(size_t)ia.y * 32 + lane]);
        uint2 r2 = __ldcg(&Hq[(size_t)ia.z * 32 + lane]);
        uint2 r3 = __ldcg(&Hq[(size_t)ia.w * 32 + lane]);
        uint2 r4 = __ldcg(&Hq[(size_t)ib.x * 32 + lane]);
        uint2 r5 = __ldcg(&Hq[(size_t)ib.y * 32 + lane]);
        uint2 r6 = __ldcg(&Hq[(size_t)ib.z * 32 + lane]);
        uint2 r7 = __ldcg(&Hq[(size_t)ib.w * 32 + lane]);
        float2 f01, f23;
        UNPACK4(r0, f01, f23);
        a0.x = fmaf(f01.x, d0, a0.x); a0.y = fmaf(f01.y, d0, a0.y);
        a0.z = fmaf(f23.x, d0, a0.z); a0.w = fmaf(f23.y, d0, a0.w);
        UNPACK4(r1, f01, f23);
        a1.x = fmaf(f01.x, d1, a1.x); a1.y = fmaf(f01.y, d1, a1.y);
        a1.z = fmaf(f23.x, d1, a1.z); a1.w = fmaf(f23.y, d1, a1.w);
        UNPACK4(r2, f01, f23);
        a2.x = fmaf(f01.x, d2, a2.x); a2.y = fmaf(f01.y, d2, a2.y);
        a2.z = fmaf(f23.x, d2, a2.z); a2.w = fmaf(f23.y, d2, a2.w);
        UNPACK4(r3, f01, f23);
        a3.x = fmaf(f01.x, d3, a3.x); a3.y = fmaf(f01.y, d3, a3.y);
        a3.z = fmaf(f23.x, d3, a3.z); a3.w = fmaf(f23.y, d3, a3.w);
        UNPACK4(r4, f01, f23);
        a0.x = fmaf(f01.x, d4, a0.x); a0.y = fmaf(f01.y, d4, a0.y);
        a0.z = fmaf(f23.x, d4, a0.z); a0.w = fmaf(f23.y, d4, a0.w);
        UNPACK4(r5, f01, f23);
        a1.x = fmaf(f01.x, d5, a1.x); a1.y = fmaf(f01.y, d5, a1.y);
        a1.z = fmaf(f23.x, d5, a1.z); a1.w = fmaf(f23.y, d5, a1.w);
        UNPACK4(r6, f01, f23);
        a2.x = fmaf(f01.x, d6, a2.x); a2.y = fmaf(f01.y, d6, a2.y);
        a2.z = fmaf(f23.x, d6, a2.z); a2.w = fmaf(f23.y, d6, a2.w);
        UNPACK4(r7, f01, f23);
        a3.x = fmaf(f01.x, d7, a3.x); a3.y = fmaf(f01.y, d7, a3.y);
        a3.z = fmaf(f23.x, d7, a3.z); a3.w = fmaf(f23.y, d7, a3.w);
    }
    for (; f < len; f++) {
        int s = __ldg(&g_ell[gw * CAP + f]);
        float d = __ldg(&g_dinv[s]);
        uint2 r = __ldcg(&Hq[(size_t)s * 32 + lane]);
        float2 f01, f23; UNPACK4(r, f01, f23);
        a0.x = fmaf(f01.x, d, a0.x); a0.y = fmaf(f01.y, d, a0.y);
        a0.z = fmaf(f23.x, d, a0.z); a0.w = fmaf(f23.y, d, a0.w);
    }
    a0.x += a1.x + a2.x + a3.x;
    a0.y += a1.y + a2.y + a3.y;
    a0.z += a1.z + a2.z + a3.z;
    a0.w += a1.w + a2.w + a3.w;

    float4 b = reinterpret_cast<const float4*>(b1)[lane];
    float4 o;
    o.x = fmaxf(fmaf(a0.x, dvn, b.x), 0.f);
    o.y = fmaxf(fmaf(a0.y, dvn, b.y), 0.f);
    o.z = fmaxf(fmaf(a0.z, dvn, b.z), 0.f);
    o.w = fmaxf(fmaf(a0.w, dvn, b.w), 0.f);
    reinterpret_cast<float4*>(g_x2)[(size_t)gw * 32 + lane] = o;
}

// ---------------- layer-2 aggregation: half-warp per node, ELL (R10) ----------
__global__ __launch_bounds__(256)
void k_agg2(float* __restrict__ out, const float* __restrict__ b2) {
    int gw   = (blockIdx.x * 256 + threadIdx.x) >> 5;
    int lane = threadIdx.x & 31;
    int n    = gw * 2 + (lane >> 4);
    int hl   = lane & 15;
    if (n >= N_NODES) return;

    const uint2* Hq = reinterpret_cast<const uint2*>(g_h2);

    float4 a0, a1, a2, a3;
    {
        uint2 r = __ldcg(&Hq[(size_t)n * 16 + hl]);
        float2 f01, f23; UNPACK4(r, f01, f23);
        a0 = make_float4(f01.x, f01.y, f23.x, f23.y);   // self (pre-scaled)
    }
    a1 = make_float4(0.f, 0.f, 0.f, 0.f);
    a2 = make_float4(0.f, 0.f, 0.f, 0.f);
    a3 = make_float4(0.f, 0.f, 0.f, 0.f);

    const int len = __ldg(&g_len[n]);
    const int4* E4 = reinterpret_cast<const int4*>(g_ell + n * CAP);
    int f = 0;

    for (; f + 8 <= len; f += 8) {
        int4 ia = __ldg(&E4[(f >> 2) + 0]);
        int4 ib = __ldg(&E4[(f >> 2) + 1]);
        uint2 r0 = __ldcg(&Hq[(size_t)ia.x * 16 + hl]);
        uint2 r1 = __ldcg(&Hq[(size_t)ia.y * 16 + hl]);
        uint2 r2 = __ldcg(&Hq[(size_t)ia.z * 16 + hl]);
        uint2 r3 = __ldcg(&Hq[(size_t)ia.w * 16 + hl]);
        uint2 r4 = __ldcg(&Hq[(size_t)ib.x * 16 + hl]);
        uint2 r5 = __ldcg(&Hq[(size_t)ib.y * 16 + hl]);
        uint2 r6 = __ldcg(&Hq[(size_t)ib.z * 16 + hl]);
        uint2 r7 = __ldcg(&Hq[(size_t)ib.w * 16 + hl]);
        float2 f01, f23;
        UNPACK4(r0, f01, f23);
        a0.x += f01.x; a0.y += f01.y; a0.z += f23.x; a0.w += f23.y;
        UNPACK4(r1, f01, f23);
        a1.x += f01.x; a1.y += f01.y; a1.z += f23.x; a1.w += f23.y;
        UNPACK4(r2, f01, f23);
        a2.x += f01.x; a2.y += f01.y; a2.z += f23.x; a2.w += f23.y;
        UNPACK4(r3, f01, f23);
        a3.x += f01.x; a3.y += f01.y; a3.z += f23.x; a3.w += f23.y;
        UNPACK4(r4, f01, f23);
        a0.x += f01.x; a0.y += f01.y; a0.z += f23.x; a0.w += f23.y;
        UNPACK4(r5, f01, f23);
        a1.x += f01.x; a1.y += f01.y; a1.z += f23.x; a1.w += f23.y;
        UNPACK4(r6, f01, f23);
        a2.x += f01.x; a2.y += f01.y; a2.z += f23.x; a2.w += f23.y;
        UNPACK4(r7, f01, f23);
        a3.x += f01.x; a3.y += f01.y; a3.z += f23.x; a3.w += f23.y;
    }
    for (; f < len; f++) {
        int s = __ldg(&g_ell[n * CAP + f]);
        uint2 r = __ldcg(&Hq[(size_t)s * 16 + hl]);
        float2 f01, f23; UNPACK4(r, f01, f23);
        a0.x += f01.x; a0.y += f01.y; a0.z += f23.x; a0.w += f23.y;
    }
    a0.x += a1.x + a2.x + a3.x;
    a0.y += a1.y + a2.y + a3.y;
    a0.z += a1.z + a2.z + a3.z;
    a0.w += a1.w + a2.w + a3.w;

    float dv = __ldg(&g_dinv[n]);
    float4 b = reinterpret_cast<const float4*>(b2)[hl];
    float4 o;
    o.x = fmaf(a0.x, dv, b.x);
    o.y = fmaf(a0.y, dv, b.y);
    o.z = fmaf(a0.z, dv, b.z);
    o.w = fmaf(a0.w, dv, b.w);
    reinterpret_cast<float4*>(out)[(size_t)n * 16 + hl] = o;
}

// ---------------- launch -------------------------------------------------------
extern "C" void kernel_launch(void* const* d_in, const int* in_sizes, int n_in,
                              void* d_out, int out_size)
{
    const float* x  = (const float*)d_in[0];
    const int*   ei = (const int*)  d_in[1];
    const float* W1 = (const float*)d_in[2];
    const float* b1 = (const float*)d_in[3];
    const float* W2 = (const float*)d_in[4];
    const float* b2 = (const float*)d_in[5];
    float* out = (float*)d_out;

    const int* srcp = ei;             // edge_index[0]
    const int* dstp = ei + N_EDGES;   // edge_index[1]

    __half *h1, *h2;
    float *x2;
    cudaGetSymbolAddress((void**)&h1, g_h1);
    cudaGetSymbolAddress((void**)&x2, g_x2);
    cudaGetSymbolAddress((void**)&h2, g_h2);

    const int SM1 = 2 * 16384 + 2 * 16384;   // A 32KB + W 32KB = 64 KB
    const int SM2 = 2 * 16384 + 1 * 16384;   // A 32KB + W 16KB = 48 KB

    static cudaStream_t s_aux = nullptr;
    static cudaEvent_t  e_fork = nullptr, e_join = nullptr;
    if (s_aux == nullptr) {
        cudaStreamCreateWithFlags(&s_aux, cudaStreamNonBlocking);
        cudaEventCreateWithFlags(&e_fork, cudaEventDisableTiming);
        cudaEventCreateWithFlags(&e_join, cudaEventDisableTiming);
        cudaFuncSetAttribute(k_gemm_mma<HID_C, false>,
                             cudaFuncAttributeMaxDynamicSharedMemorySize, SM1);
        cudaFuncSetAttribute(k_gemm_mma<OUT_C, true>,
                             cudaFuncAttributeMaxDynamicSharedMemorySize, SM2);
    }

    const int gemm_blocks = (N_NODES + 127) / 128;   // 391

    // fork point at the start of the call (main stream)
    cudaEventRecord(e_fork, 0);
    cudaStreamWaitEvent(s_aux, e_fork, 0);

    // ---- GEMM1 on aux (no dinv dependency) ----
    k_gemm_mma<HID_C, false><<<gemm_blocks, 128, SM1, s_aux>>>(x, W1, h1);
    cudaEventRecord(e_join, s_aux);

    // ---- ELL build on the main stream (overlaps GEMM1) ----
    k_place_ell<<<(N_EDGES / 4 + 255) / 256, 256>>>(srcp, dstp);
    k_dinv     <<<(N_NODES + 255) / 256, 256>>>();

    // ---- join, then layer 1 aggregation ----
    cudaStreamWaitEvent(0, e_join, 0);
    k_agg1<<<(N_NODES * 32 + 255) / 256, 256>>>(b1);

    // ---- layer 2 ----
    k_gemm_mma<OUT_C, true><<<gemm_blocks, 128, SM2, 0>>>(x2, W2, h2);
    k_agg2<<<((N_NODES + 1) / 2 * 32 + 255) / 256, 256>>>(out, b2);
}

// round 14
// speedup vs baseline: 1.9420x; 1.0446x over previous
#include <cuda_runtime.h>
#include <cuda_fp16.h>
#include <stdint.h>

#define N_NODES 50000
#define N_EDGES 800000
#define IN_C    128
#define HID_C   128
#define OUT_C   64
#define CAP     64          // ELL capacity per node (P(deg>48) ~ 1e-10)

typedef unsigned long long ull;
union H4 { uint2 u; __half2 h[2]; };
union H8 { uint4 u; __half2 h[4]; };

// ---------------- scratch (static device globals; zero-initialized) ----------
__device__ int    g_cnt [N_NODES];           // ALWAYS zero between calls
__device__ int    g_len [N_NODES];
__device__ int    g_ell [N_NODES * CAP];     // ELL adjacency (by dst)
__device__ float  g_dinv[N_NODES];
__device__ __half g_h1  [N_NODES * HID_C];   // UNSCALED GEMM1 output (fp16)
__device__ __half g_h2  [N_NODES * OUT_C];   // pre-scaled GEMM2 output (fp16)

// ---------------- PTX helpers --------------------------------------------------
__device__ __forceinline__ uint32_t smem_u32(const void* p) {
    uint32_t a;
    asm("{ .reg .u64 t; cvta.to.shared.u64 t, %1; cvt.u32.u64 %0, t; }"
        : "=r"(a) : "l"(p));
    return a;
}

__device__ __forceinline__ void ldsm_x4(uint32_t& r0, uint32_t& r1,
                                        uint32_t& r2, uint32_t& r3, uint32_t addr) {
    asm volatile("ldmatrix.sync.aligned.m8n8.x4.shared.b16 {%0,%1,%2,%3}, [%4];"
                 : "=r"(r0), "=r"(r1), "=r"(r2), "=r"(r3) : "r"(addr));
}

__device__ __forceinline__ void ldsm_x4_t(uint32_t& r0, uint32_t& r1,
                                          uint32_t& r2, uint32_t& r3, uint32_t addr) {
    asm volatile("ldmatrix.sync.aligned.m8n8.x4.trans.shared.b16 {%0,%1,%2,%3}, [%4];"
                 : "=r"(r0), "=r"(r1), "=r"(r2), "=r"(r3) : "r"(addr));
}

__device__ __forceinline__ void mma16816(float* c, const uint32_t* a,
                                         uint32_t b0, uint32_t b1) {
    asm volatile("mma.sync.aligned.m16n8k16.row.col.f32.f16.f16.f32 "
                 "{%0,%1,%2,%3}, {%4,%5,%6,%7}, {%8,%9}, {%0,%1,%2,%3};"
                 : "+f"(c[0]), "+f"(c[1]), "+f"(c[2]), "+f"(c[3])
                 : "r"(a[0]), "r"(a[1]), "r"(a[2]), "r"(a[3]), "r"(b0), "r"(b1));
}

// ---------------- ELL build: count + place in ONE kernel ----------------------
__global__ void k_place_ell(const int* __restrict__ src, const int* __restrict__ dst) {
    int t = blockIdx.x * blockDim.x + threadIdx.x;
    if (t >= N_EDGES / 4) return;
    int4 d4 = reinterpret_cast<const int4*>(dst)[t];
    int4 s4 = reinterpret_cast<const int4*>(src)[t];
    int i0 = atomicAdd(&g_cnt[d4.x], 1);
    int i1 = atomicAdd(&g_cnt[d4.y], 1);
    int i2 = atomicAdd(&g_cnt[d4.z], 1);
    int i3 = atomicAdd(&g_cnt[d4.w], 1);
    if (i0 < CAP) g_ell[d4.x * CAP + i0] = s4.x;
    if (i1 < CAP) g_ell[d4.y * CAP + i1] = s4.y;
    if (i2 < CAP) g_ell[d4.z * CAP + i2] = s4.z;
    if (i3 < CAP) g_ell[d4.w * CAP + i3] = s4.w;
}

__global__ void k_dinv() {
    int i = blockIdx.x * blockDim.x + threadIdx.x;
    if (i >= N_NODES) return;
    int c = g_cnt[i];
    g_len[i]  = (c < CAP) ? c : CAP;
    g_dinv[i] = rsqrtf(1.0f + (float)c);           // +1 self loop
    g_cnt[i]  = 0;                                 // restore zero invariant
}

// ---------------- GEMM1 via mma.sync m16n8k16 (unchanged from R13) ------------
template <int COUT, bool PRESCALE>
__global__ __launch_bounds__(128)
void k_gemm_mma(const float* __restrict__ X, const float* __restrict__ W,
                __half* __restrict__ H)
{
    constexpr int NT   = COUT / 8;
    constexpr int NJP  = NT / 2;
    constexpr int SUBB = 16384;

    extern __shared__ char smem[];
    char* sA = smem;
    char* sW = smem + 2 * SUBB;

    const int tid  = threadIdx.x;
    const int wid  = tid >> 5;
    const int lane = tid & 31;
    const int row0 = blockIdx.x * 128;

    for (int i = tid; i < 128 * 16; i += 128) {
        int r = i >> 4, g = i & 15;
        int gr = row0 + r;
        float4 v0 = make_float4(0.f, 0.f, 0.f, 0.f);
        float4 v1 = v0;
        if (gr < N_NODES) {
            const float4* p = reinterpret_cast<const float4*>(X + (size_t)gr * IN_C + g * 8);
            v0 = p[0]; v1 = p[1];
        }
        H8 h;
        h.h[0] = __floats2half2_rn(v0.x, v0.y);
        h.h[1] = __floats2half2_rn(v0.z, v0.w);
        h.h[2] = __floats2half2_rn(v1.x, v1.y);
        h.h[3] = __floats2half2_rn(v1.z, v1.w);
        int sub = g >> 3, gg = g & 7;
        int off = r * 128 + gg * 16;
        off ^= (off >> 3) & 0x70;
        *reinterpret_cast<uint4*>(sA + sub * SUBB + off) = h.u;
    }
    for (int i = tid; i < 128 * (COUT / 8); i += 128) {
        int r = i / (COUT / 8), g = i % (COUT / 8);
        const float4* p = reinterpret_cast<const float4*>(W + (size_t)r * COUT + g * 8);
        float4 v0 = p[0], v1 = p[1];
        H8 h;
        h.h[0] = __floats2half2_rn(v0.x, v0.y);
        h.h[1] = __floats2half2_rn(v0.z, v0.w);
        h.h[2] = __floats2half2_rn(v1.x, v1.y);
        h.h[3] = __floats2half2_rn(v1.z, v1.w);
        int sub = g >> 3, gg = g & 7;
        int off = r * 128 + gg * 16;
        off ^= (off >> 3) & 0x70;
        *reinterpret_cast<uint4*>(sW + sub * SUBB + off) = h.u;
    }
    __syncthreads();

    const uint32_t sA32 = smem_u32(sA);
    const uint32_t sW32 = smem_u32(sW);

    const int arow = (lane & 7) + ((lane & 8) ? 8 : 0);
    const int cgb  = (lane >> 4) & 1;
    const int xorv = (lane & 7) << 4;

    float acc[2][NT][4];
#pragma unroll
    for (int mt = 0; mt < 2; mt++)
#pragma unroll
        for (int nt = 0; nt < NT; nt++)
#pragma unroll
            for (int q = 0; q < 4; q++) acc[mt][nt][q] = 0.f;

    const int R = wid * 32;

#pragma unroll
    for (int ks = 0; ks < 8; ks++) {
        uint32_t a[2][4];
        const int subA = ks >> 2;
        const int grpA = (ks & 3) * 2 + cgb;
#pragma unroll
        for (int mt = 0; mt < 2; mt++) {
            int off = (R + mt * 16 + arow) * 128 + ((grpA * 16) ^ xorv);
            ldsm_x4(a[mt][0], a[mt][1], a[mt][2], a[mt][3],
                    sA32 + subA * SUBB + off);
        }
#pragma unroll
        for (int jp = 0; jp < NJP; jp++) {
            uint32_t b0, b1, b2, b3;
            const int subB = jp >> 2;
            const int grpB = (jp & 3) * 2 + cgb;
            int off = (ks * 16 + arow) * 128 + ((grpB * 16) ^ xorv);
            ldsm_x4_t(b0, b1, b2, b3, sW32 + subB * SUBB + off);
#pragma unroll
            for (int mt = 0; mt < 2; mt++) {
                mma16816(acc[mt][2 * jp + 0], a[mt], b0, b1);
                mma16816(acc[mt][2 * jp + 1], a[mt], b2, b3);
            }
        }
    }

    const int erow = lane >> 2;
    const int ecol = (lane & 3) * 2;
#pragma unroll
    for (int mt = 0; mt < 2; mt++) {
        int gr0 = row0 + R + mt * 16 + erow;
        int gr1 = gr0 + 8;
        float dv0 = 1.f, dv1 = 1.f;
        if (PRESCALE) {
            if (gr0 < N_NODES) dv0 = g_dinv[gr0];
            if (gr1 < N_NODES) dv1 = g_dinv[gr1];
        }
#pragma unroll
        for (int nt = 0; nt < NT; nt++) {
            if (gr0 < N_NODES) {
                __half2 h = __floats2half2_rn(acc[mt][nt][0] * dv0,
                                              acc[mt][nt][1] * dv0);
                *reinterpret_cast<__half2*>(H + (size_t)gr0 * COUT + nt * 8 + ecol) = h;
            }
            if (gr1 < N_NODES) {
                __half2 h = __floats2half2_rn(acc[mt][nt][2] * dv1,
                                              acc[mt][nt][3] * dv1);
                *reinterpret_cast<__half2*>(H + (size_t)gr1 * COUT + nt * 8 + ecol) = h;
            }
        }
    }
}

// ---------------- FUSED agg1 + GEMM2 -------------------------------------------
// 512 threads per block, 128 nodes per block.
// Phase A: 16 warps aggregate 8 nodes each (identical to R13 agg1), writing
//          relu(dinv*(...)+b1) as fp16 into a swizzled smem tile.
// Phase B: warps 0-7 run m16n8k16 GEMM2 (K=128 from smem), writing pre-scaled
//          fp16 h2 to global.
__global__ __launch_bounds__(512)
void k_agg1_gemm2(const float* __restrict__ b1, const float* __restrict__ W2)
{
    constexpr int SUBB = 16384;

    extern __shared__ char smem[];
    char* sX = smem;                    // x2 tile: 2 subtiles (128 x 64h) = 32 KB
    char* sW = smem + 2 * SUBB;         // W2 tile: 1 subtile = 16 KB

    const int tid  = threadIdx.x;
    const int wid  = tid >> 5;          // 0..15
    const int lane = tid & 31;
    const int row0 = blockIdx.x * 128;

    // ---- W2 tile: fp32 -> fp16, swizzled (128 x 64) ----
    for (int i = tid; i < 128 * 8; i += 512) {
        int r = i >> 3, g = i & 7;
        const float4* p = reinterpret_cast<const float4*>(W2 + (size_t)r * OUT_C + g * 8);
        float4 v0 = p[0], v1 = p[1];
        H8 h;
        h.h[0] = __floats2half2_rn(v0.x, v0.y);
        h.h[1] = __floats2half2_rn(v0.z, v0.w);
        h.h[2] = __floats2half2_rn(v1.x, v1.y);
        h.h[3] = __floats2half2_rn(v1.z, v1.w);
        int off = r * 128 + g * 16;
        off ^= (off >> 3) & 0x70;
        *reinterpret_cast<uint4*>(sW + off) = h.u;
    }

    // ---- Phase A: aggregation into smem x2 tile ----
    const uint2* Hq = reinterpret_cast<const uint2*>(g_h1);
    float4 bv = reinterpret_cast<const float4*>(b1)[lane];   // lane's 4 channels

    // smem x2 address for (row r, lane): sub = lane>>4, col byte = (8*lane)&127
    const int xsub = lane >> 4;
    const int xcol = (8 * lane) & 127;

#define UNPACK4(r, f01, f23) { H4 _t; _t.u = (r); \
        f01 = __half22float2(_t.h[0]); f23 = __half22float2(_t.h[1]); }

#pragma unroll 1
    for (int j = 0; j < 8; j++) {
        const int r  = wid * 8 + j;           // tile row 0..127
        const int n  = row0 + r;
        float4 a0 = make_float4(0.f, 0.f, 0.f, 0.f);
        float4 a1 = a0, a2 = a0, a3 = a0;
        float dvn = 0.f;

        if (n < N_NODES) {
            dvn = __ldg(&g_dinv[n]);
            {
                uint2 rr = __ldcg(&Hq[(size_t)n * 32 + lane]);
                float2 f01, f23; UNPACK4(rr, f01, f23);
                a0 = make_float4(f01.x * dvn, f01.y * dvn, f23.x * dvn, f23.y * dvn);
            }
            const int len = __ldg(&g_len[n]);
            const int4* E4 = reinterpret_cast<const int4*>(g_ell + n * CAP);
            int f = 0;
            for (; f + 8 <= len; f += 8) {
                int4 ia = __ldg(&E4[(f >> 2) + 0]);
                int4 ib = __ldg(&E4[(f >> 2) + 1]);
                float d0 = __ldg(&g_dinv[ia.x]), d1 = __ldg(&g_dinv[ia.y]);
                float d2 = __ldg(&g_dinv[ia.z]), d3 = __ldg(&g_dinv[ia.w]);
                float d4 = __ldg(&g_dinv[ib.x]), d5 = __ldg(&g_dinv[ib.y]);
                float d6 = __ldg(&g_dinv[ib.z]), d7 = __ldg(&g_dinv[ib.w]);
                uint2 r0 = __ldcg(&Hq[(size_t)ia.x * 32 + lane]);
                uint2 r1 = __ldcg(&Hq[(size_t)ia.y * 32 + lane]);
                uint2 r2 = __ldcg(&Hq[(size_t)ia.z * 32 + lane]);
                uint2 r3 = __ldcg(&Hq[(size_t)ia.w * 32 + lane]);
                uint2 r4 = __ldcg(&Hq[(size_t)ib.x * 32 + lane]);
                uint2 r5 = __ldcg(&Hq[(size_t)ib.y * 32 + lane]);
                uint2 r6 = __ldcg(&Hq[(size_t)ib.z * 32 + lane]);
                uint2 r7 = __ldcg(&Hq[(size_t)ib.w * 32 + lane]);
                float2 f01, f23;
                UNPACK4(r0, f01, f23);
                a0.x = fmaf(f01.x, d0, a0.x); a0.y = fmaf(f01.y, d0, a0.y);
                a0.z = fmaf(f23.x, d0, a0.z); a0.w = fmaf(f23.y, d0, a0.w);
                UNPACK4(r1, f01, f23);
                a1.x = fmaf(f01.x, d1, a1.x); a1.y = fmaf(f01.y, d1, a1.y);
                a1.z = fmaf(f23.x, d1, a1.z); a1.w = fmaf(f23.y, d1, a1.w);
                UNPACK4(r2, f01, f23);
                a2.x = fmaf(f01.x, d2, a2.x); a2.y = fmaf(f01.y, d2, a2.y);
                a2.z = fmaf(f23.x, d2, a2.z); a2.w = fmaf(f23.y, d2, a2.w);
                UNPACK4(r3, f01, f23);
                a3.x = fmaf(f01.x, d3, a3.x); a3.y = fmaf(f01.y, d3, a3.y);
                a3.z = fmaf(f23.x, d3, a3.z); a3.w = fmaf(f23.y, d3, a3.w);
                UNPACK4(r4, f01, f23);
                a0.x = fmaf(f01.x, d4, a0.x); a0.y = fmaf(f01.y, d4, a0.y);
                a0.z = fmaf(f23.x, d4, a0.z); a0.w = fmaf(f23.y, d4, a0.w);
                UNPACK4(r5, f01, f23);
                a1.x = fmaf(f01.x, d5, a1.x); a1.y = fmaf(f01.y, d5, a1.y);
                a1.z = fmaf(f23.x, d5, a1.z); a1.w = fmaf(f23.y, d5, a1.w);
                UNPACK4(r6, f01, f23);
                a2.x = fmaf(f01.x, d6, a2.x); a2.y = fmaf(f01.y, d6, a2.y);
                a2.z = fmaf(f23.x, d6, a2.z); a2.w = fmaf(f23.y, d6, a2.w);
                UNPACK4(r7, f01, f23);
                a3.x = fmaf(f01.x, d7, a3.x); a3.y = fmaf(f01.y, d7, a3.y);
                a3.z = fmaf(f23.x, d7, a3.z); a3.w = fmaf(f23.y, d7, a3.w);
            }
            for (; f < len; f++) {
                int s = __ldg(&g_ell[n * CAP + f]);
                float d = __ldg(&g_dinv[s]);
                uint2 rr = __ldcg(&Hq[(size_t)s * 32 + lane]);
                float2 f01, f23; UNPACK4(rr, f01, f23);
                a0.x = fmaf(f01.x, d, a0.x); a0.y = fmaf(f01.y, d, a0.y);
                a0.z = fmaf(f23.x, d, a0.z); a0.w = fmaf(f23.y, d, a0.w);
            }
            a0.x += a1.x + a2.x + a3.x;
            a0.y += a1.y + a2.y + a3.y;
            a0.z += a1.z + a2.z + a3.z;
            a0.w += a1.w + a2.w + a3.w;
        }

        // relu(dinv*acc + b) -> fp16 -> smem (zeros for OOB rows)
        float ox = 0.f, oy = 0.f, oz = 0.f, ow = 0.f;
        if (n < N_NODES) {
            ox = fmaxf(fmaf(a0.x, dvn, bv.x), 0.f);
            oy = fmaxf(fmaf(a0.y, dvn, bv.y), 0.f);
            oz = fmaxf(fmaf(a0.z, dvn, bv.z), 0.f);
            ow = fmaxf(fmaf(a0.w, dvn, bv.w), 0.f);
        }
        ull pk;
        {
            __half2 h0 = __floats2half2_rn(ox, oy);
            __half2 h1v = __floats2half2_rn(oz, ow);
            uint32_t u0 = *reinterpret_cast<uint32_t*>(&h0);
            uint32_t u1 = *reinterpret_cast<uint32_t*>(&h1v);
            pk = ((ull)u1 << 32) | u0;
        }
        int off = r * 128 + xcol;
        off ^= (off >> 3) & 0x70;
        *reinterpret_cast<ull*>(sX + xsub * SUBB + off) = pk;
    }
    __syncthreads();

    // ---- Phase B: GEMM2 (warps 0-7, 16 rows each, COUT=64) ----
    if (wid < 8) {
        const uint32_t sX32 = smem_u32(sX);
        const uint32_t sW32 = smem_u32(sW);

        const int arow = (lane & 7) + ((lane & 8) ? 8 : 0);
        const int cgb  = (lane >> 4) & 1;
        const int xorv = (lane & 7) << 4;
        const int R = wid * 16;

        float acc[8][4];
#pragma unroll
        for (int nt = 0; nt < 8; nt++)
#pragma unroll
            for (int q = 0; q < 4; q++) acc[nt][q] = 0.f;

#pragma unroll
        for (int ks = 0; ks < 8; ks++) {
            uint32_t a[4];
            const int subA = ks >> 2;
            const int grpA = (ks & 3) * 2 + cgb;
            int offA = (R + arow) * 128 + ((grpA * 16) ^ xorv);
            ldsm_x4(a[0], a[1], a[2], a[3], sX32 + subA * SUBB + offA);
#pragma unroll
            for (int jp = 0; jp < 4; jp++) {
                uint32_t b0, b1, b2, b3;
                const int grpB = jp * 2 + cgb;
                int offB = (ks * 16 + arow) * 128 + ((grpB * 16) ^ xorv);
                ldsm_x4_t(b0, b1, b2, b3, sW32 + offB);
                mma16816(acc[2 * jp + 0], a, b0, b1);
                mma16816(acc[2 * jp + 1], a, b2, b3);
            }
        }

        const int erow = lane >> 2;
        const int ecol = (lane & 3) * 2;
        int gr0 = row0 + R + erow;
        int gr1 = gr0 + 8;
        float dv0 = 1.f, dv1 = 1.f;
        if (gr0 < N_NODES) dv0 = g_dinv[gr0];
        if (gr1 < N_NODES) dv1 = g_dinv[gr1];
#pragma unroll
        for (int nt = 0; nt < 8; nt++) {
            if (gr0 < N_NODES) {
                __half2 h = __floats2half2_rn(acc[nt][0] * dv0, acc[nt][1] * dv0);
                *reinterpret_cast<__half2*>(g_h2 + (size_t)gr0 * OUT_C + nt * 8 + ecol) = h;
            }
            if (gr1 < N_NODES) {
                __half2 h = __floats2half2_rn(acc[nt][2] * dv1, acc[nt][3] * dv1);
                *reinterpret_cast<__half2*>(g_h2 + (size_t)gr1 * OUT_C + nt * 8 + ecol) = h;
            }
        }
    }
}

// ---------------- layer-2 aggregation: half-warp per node, ELL (R10) ----------
__global__ __launch_bounds__(256)
void k_agg2(float* __restrict__ out, const float* __restrict__ b2) {
    int gw   = (blockIdx.x * 256 + threadIdx.x) >> 5;
    int lane = threadIdx.x & 31;
    int n    = gw * 2 + (lane >> 4);
    int hl   = lane & 15;
    if (n >= N_NODES) return;

    const uint2* Hq = reinterpret_cast<const uint2*>(g_h2);

    float4 a0, a1, a2, a3;
    {
        uint2 r = __ldcg(&Hq[(size_t)n * 16 + hl]);
        float2 f01, f23; UNPACK4(r, f01, f23);
        a0 = make_float4(f01.x, f01.y, f23.x, f23.y);   // self (pre-scaled)
    }
    a1 = make_float4(0.f, 0.f, 0.f, 0.f);
    a2 = make_float4(0.f, 0.f, 0.f, 0.f);
    a3 = make_float4(0.f, 0.f, 0.f, 0.f);

    const int len = __ldg(&g_len[n]);
    const int4* E4 = reinterpret_cast<const int4*>(g_ell + n * CAP);
    int f = 0;

    for (; f + 8 <= len; f += 8) {
        int4 ia = __ldg(&E4[(f >> 2) + 0]);
        int4 ib = __ldg(&E4[(f >> 2) + 1]);
        uint2 r0 = __ldcg(&Hq[(size_t)ia.x * 16 + hl]);
        uint2 r1 = __ldcg(&Hq[(size_t)ia.y * 16 + hl]);
        uint2 r2 = __ldcg(&Hq[(size_t)ia.z * 16 + hl]);
        uint2 r3 = __ldcg(&Hq[(size_t)ia.w * 16 + hl]);
        uint2 r4 = __ldcg(&Hq[(size_t)ib.x * 16 + hl]);
        uint2 r5 = __ldcg(&Hq[(size_t)ib.y * 16 + hl]);
        uint2 r6 = __ldcg(&Hq[(size_t)ib.z * 16 + hl]);
        uint2 r7 = __ldcg(&Hq[(size_t)ib.w * 16 + hl]);
        float2 f01, f23;
        UNPACK4(r0, f01, f23);
        a0.x += f01.x; a0.y += f01.y; a0.z += f23.x; a0.w += f23.y;
        UNPACK4(r1, f01, f23);
        a1.x += f01.x; a1.y += f01.y; a1.z += f23.x; a1.w += f23.y;
        UNPACK4(r2, f01, f23);
        a2.x += f01.x; a2.y += f01.y; a2.z += f23.x; a2.w += f23.y;
        UNPACK4(r3, f01, f23);
        a3.x += f01.x; a3.y += f01.y; a3.z += f23.x; a3.w += f23.y;
        UNPACK4(r4, f01, f23);
        a0.x += f01.x; a0.y += f01.y; a0.z += f23.x; a0.w += f23.y;
        UNPACK4(r5, f01, f23);
        a1.x += f01.x; a1.y += f01.y; a1.z += f23.x; a1.w += f23.y;
        UNPACK4(r6, f01, f23);
        a2.x += f01.x; a2.y += f01.y; a2.z += f23.x; a2.w += f23.y;
        UNPACK4(r7, f01, f23);
        a3.x += f01.x; a3.y += f01.y; a3.z += f23.x; a3.w += f23.y;
    }
    for (; f < len; f++) {
        int s = __ldg(&g_ell[n * CAP + f]);
        uint2 r = __ldcg(&Hq[(size_t)s * 16 + hl]);
        float2 f01, f23; UNPACK4(r, f01, f23);
        a0.x += f01.x; a0.y += f01.y; a0.z += f23.x; a0.w += f23.y;
    }
    a0.x += a1.x + a2.x + a3.x;
    a0.y += a1.y + a2.y + a3.y;
    a0.z += a1.z + a2.z + a3.z;
    a0.w += a1.w + a2.w + a3.w;

    float dv = __ldg(&g_dinv[n]);
    float4 b = reinterpret_cast<const float4*>(b2)[hl];
    float4 o;
    o.x = fmaf(a0.x, dv, b.x);
    o.y = fmaf(a0.y, dv, b.y);
    o.z = fmaf(a0.z, dv, b.z);
    o.w = fmaf(a0.w, dv, b.w);
    reinterpret_cast<float4*>(out)[(size_t)n * 16 + hl] = o;
}

// ---------------- launch -------------------------------------------------------
extern "C" void kernel_launch(void* const* d_in, const int* in_sizes, int n_in,
                              void* d_out, int out_size)
{
    const float* x  = (const float*)d_in[0];
    const int*   ei = (const int*)  d_in[1];
    const float* W1 = (const float*)d_in[2];
    const float* b1 = (const float*)d_in[3];
    const float* W2 = (const float*)d_in[4];
    const float* b2 = (const float*)d_in[5];
    float* out = (float*)d_out;

    const int* srcp = ei;             // edge_index[0]
    const int* dstp = ei + N_EDGES;   // edge_index[1]

    __half* h1;
    cudaGetSymbolAddress((void**)&h1, g_h1);

    const int SM1 = 2 * 16384 + 2 * 16384;   // gemm1: A 32KB + W 32KB
    const int SMF = 2 * 16384 + 1 * 16384;   // fused: x2 32KB + W2 16KB

    static cudaStream_t s_aux = nullptr;
    static cudaEvent_t  e_fork = nullptr, e_join = nullptr;
    if (s_aux == nullptr) {
        cudaStreamCreateWithFlags(&s_aux, cudaStreamNonBlocking);
        cudaEventCreateWithFlags(&e_fork, cudaEventDisableTiming);
        cudaEventCreateWithFlags(&e_join, cudaEventDisableTiming);
        cudaFuncSetAttribute(k_gemm_mma<HID_C, false>,
                             cudaFuncAttributeMaxDynamicSharedMemorySize, SM1);
        cudaFuncSetAttribute(k_agg1_gemm2,
                             cudaFuncAttributeMaxDynamicSharedMemorySize, SMF);
    }

    const int tile_blocks = (N_NODES + 127) / 128;   // 391

    // fork point at the start of the call (main stream)
    cudaEventRecord(e_fork, 0);
    cudaStreamWaitEvent(s_aux, e_fork, 0);

    // ---- GEMM1 on aux (no dinv dependency) ----
    k_gemm_mma<HID_C, false><<<tile_blocks, 128, SM1, s_aux>>>(x, W1, h1);
    cudaEventRecord(e_join, s_aux);

    // ---- ELL build on the main stream (overlaps GEMM1) ----
    k_place_ell<<<(N_EDGES / 4 + 255) / 256, 256>>>(srcp, dstp);
    k_dinv     <<<(N_NODES + 255) / 256, 256>>>();

    // ---- join, then FUSED agg1 + GEMM2 ----
    cudaStreamWaitEvent(0, e_join, 0);
    k_agg1_gemm2<<<tile_blocks, 512, SMF>>>(b1, W2);

    // ---- layer-2 aggregation ----
    k_agg2<<<((N_NODES + 1) / 2 * 32 + 255) / 256, 256>>>(out, b2);
}